// round 9
// baseline (speedup 1.0000x reference)
#include <cuda_runtime.h>
#include <math.h>

#define N_    1024
#define H_    12
#define C1_   384
#define C2_   128
#define COUT_ 384
#define NPROJ 1152
#define NFEAT 2112
#define QB    4
#define TM    32
#define PITCH 132

#define W2DS 0.5773502691896258f
#define SCW  0.14433756729740643f
#define PTW  0.1360827634879543f

typedef unsigned long long u64;

__device__ __forceinline__ void fma2(u64& acc, u64 a, u64 b) {
    asm("fma.rn.f32x2 %0, %1, %2, %0;" : "+l"(acc) : "l"(a), "l"(b));
}
__device__ __forceinline__ void mul2(u64& a, u64 b) {
    asm("mul.rn.f32x2 %0, %0, %1;" : "+l"(a) : "l"(b));
}
__device__ __forceinline__ u64 pack2(float a) {
    u64 r;
    asm("mov.b64 %0, {%1, %1};" : "=l"(r) : "f"(a));
    return r;
}
__device__ __forceinline__ unsigned smem_u32(const void* p) {
    return (unsigned)__cvta_generic_to_shared(p);
}
__device__ __forceinline__ void cpa16(unsigned dst, const void* src) {
    asm volatile("cp.async.cg.shared.global [%0], [%1], 16;" :: "r"(dst), "l"(src));
}

// ---------------- scratch ----------------
__device__ float g_proj [N_ * NPROJ];
__device__ float g_qpt  [N_ * 144];
__device__ float g_kpt  [N_ * 144];
__device__ float g_vpt  [N_ * 288];
__device__ float g_qaug [N_ * H_ * 32];
__device__ float g_kaug [N_ * H_ * 32];
__device__ float g_P    [(long)N_ * H_ * 1024];   // unnormalized probs
__device__ float g_vm   [(long)N_ * H_ * 64];     // merged v: 32 u64/row (20 used)
__device__ float g_feat [(long)N_ * NFEAT];

// ---------------- kernel A: fused projection GEMM ----------------
__global__ __launch_bounds__(256) void proj_gemm_kernel(
    const float* __restrict__ A,
    const float* __restrict__ wq,  const float* __restrict__ bq,
    const float* __restrict__ wkv, const float* __restrict__ bkv,
    const float* __restrict__ wqp, const float* __restrict__ bqp,
    const float* __restrict__ wkvp,const float* __restrict__ bkvp)
{
    __shared__ float As[16][64];
    __shared__ float Bs[16][68];
    int bm = blockIdx.x * 64, bn = blockIdx.y * 64;
    int tid = threadIdx.x;
    int tx = tid & 15, ty = tid >> 4;
    int lm = tid >> 2, lk4 = (tid & 3) * 4;
    int bk = tid >> 4, bn4 = (tid & 15) * 4;
    u64 acc01[4] = {0,0,0,0}, acc23[4] = {0,0,0,0};

    for (int k0 = 0; k0 < C1_; k0 += 16) {
        float4 av = *(const float4*)&A[(bm + lm) * C1_ + k0 + lk4];
        As[lk4+0][lm] = av.x; As[lk4+1][lm] = av.y;
        As[lk4+2][lm] = av.z; As[lk4+3][lm] = av.w;
        int kg = k0 + bk;
        #pragma unroll
        for (int jj = 0; jj < 4; jj++) {
            int j = bn + bn4 + jj;
            float v;
            if      (j < 192) v = wq  [kg * 192 + j];
            else if (j < 576) v = wkv [kg * 384 + (j - 192)];
            else if (j < 720) v = wqp [kg * 144 + (j - 576)];
            else              v = wkvp[kg * 432 + (j - 720)];
            Bs[bk][bn4 + jj] = v;
        }
        __syncthreads();
        #pragma unroll
        for (int kk = 0; kk < 16; kk++) {
            float4 a4 = *(const float4*)&As[kk][ty * 4];
            ulonglong2 b2 = *(const ulonglong2*)&Bs[kk][tx * 4];
            float a[4] = {a4.x, a4.y, a4.z, a4.w};
            #pragma unroll
            for (int i = 0; i < 4; i++) {
                u64 ai = pack2(a[i]);
                fma2(acc01[i], ai, b2.x);
                fma2(acc23[i], ai, b2.y);
            }
        }
        __syncthreads();
    }
    #pragma unroll
    for (int i = 0; i < 4; i++) {
        float2 lo = *(float2*)&acc01[i];
        float2 hi = *(float2*)&acc23[i];
        float accv[4] = {lo.x, lo.y, hi.x, hi.y};
        #pragma unroll
        for (int j = 0; j < 4; j++) {
            int jg = bn + tx * 4 + j;
            float bias;
            if      (jg < 192) bias = bq  [jg];
            else if (jg < 576) bias = bkv [jg - 192];
            else if (jg < 720) bias = bqp [jg - 576];
            else               bias = bkvp[jg - 720];
            g_proj[(bm + ty * 4 + i) * NPROJ + jg] = accv[j] + bias;
        }
    }
}

// ---------------- kernel B: transform + aug vectors + merged v ----------------
__global__ __launch_bounds__(192) void transform_kernel(
    const float* __restrict__ rot, const float* __restrict__ trans,
    const float* __restrict__ tpw)
{
    int n = blockIdx.x;
    int tid = threadIdx.x;
    __shared__ float sn2[192];

    const float* pr = g_proj + n * NPROJ;
    float r00 = rot[n*9+0], r01 = rot[n*9+1], r02 = rot[n*9+2];
    float r10 = rot[n*9+3], r11 = rot[n*9+4], r12 = rot[n*9+5];
    float r20 = rot[n*9+6], r21 = rot[n*9+7], r22 = rot[n*9+8];
    float t0 = trans[n*3+0], t1 = trans[n*3+1], t2 = trans[n*3+2];

    float nrm = 0.f;
    if (tid < 48) {
        int pp = tid;
        float px = pr[576 +       pp];
        float py = pr[576 +  48 + pp];
        float pz = pr[576 +  96 + pp];
        float gx = r00*px + r01*py + r02*pz + t0;
        float gy = r10*px + r11*py + r12*pz + t1;
        float gz = r20*px + r21*py + r22*pz + t2;
        int h = pp >> 2, p = pp & 3;
        float* o = g_qpt + n * 144 + h * 12 + p * 3;
        o[0] = gx; o[1] = gy; o[2] = gz;
        nrm = gx*gx + gy*gy + gz*gz;
    } else {
        int pp = tid - 48;
        float px = pr[720 +       pp];
        float py = pr[720 + 144 + pp];
        float pz = pr[720 + 288 + pp];
        float gx = r00*px + r01*py + r02*pz + t0;
        float gy = r10*px + r11*py + r12*pz + t1;
        float gz = r20*px + r21*py + r22*pz + t2;
        int h = pp / 12, r = pp % 12;
        if (r < 4) {
            float* o = g_kpt + n * 144 + h * 12 + r * 3;
            o[0] = gx; o[1] = gy; o[2] = gz;
            nrm = gx*gx + gy*gy + gz*gz;
        } else {
            float* o = g_vpt + n * 288 + h * 24 + (r - 4) * 3;
            o[0] = gx; o[1] = gy; o[2] = gz;
        }
    }
    sn2[tid] = nrm;
    __syncthreads();
    if (tid < H_) {
        int h = tid;
        float q2 = 0.f, k2 = 0.f;
        #pragma unroll
        for (int p = 0; p < 4; p++) q2 += sn2[h * 4 + p];
        #pragma unroll
        for (int r = 0; r < 4; r++) k2 += sn2[48 + h * 12 + r];

        float tp = tpw[h];
        float spv = tp > 20.f ? tp : log1pf(__expf(tp));
        float pw = PTW * spv;

        float* qa = g_qaug + (n * H_ + h) * 32;
        float* ka = g_kaug + (n * H_ + h) * 32;
        #pragma unroll
        for (int c = 0; c < 16; c++) {
            qa[c] = SCW * pr[h * 16 + c];
            ka[c] = pr[192 + h * 32 + c];
        }
        #pragma unroll
        for (int c = 0; c < 12; c++) {
            qa[16 + c] = pw * g_qpt[n * 144 + h * 12 + c];
            ka[16 + c] = g_kpt[n * 144 + h * 12 + c];
        }
        qa[28] = -0.5f * pw * q2; qa[29] = 1.f; qa[30] = 0.f; qa[31] = 0.f;
        ka[28] = 1.f; ka[29] = -0.5f * pw * k2; ka[30] = 0.f; ka[31] = 0.f;

        // merged v row: u64 j<8 -> vs pairs, 8<=j<20 -> vp pairs, rest 0
        float2* vm = (float2*)&g_vm[((long)n * H_ + h) * 64];
        #pragma unroll
        for (int j = 0; j < 8; j++)
            vm[j] = make_float2(pr[192 + h * 32 + 16 + 2*j],
                                pr[192 + h * 32 + 16 + 2*j + 1]);
        #pragma unroll
        for (int j = 8; j < 20; j++)
            vm[j] = make_float2(g_vpt[n * 288 + h * 24 + 2*(j-8)],
                                g_vpt[n * 288 + h * 24 + 2*(j-8) + 1]);
        #pragma unroll
        for (int j = 20; j < 32; j++)
            vm[j] = make_float2(0.f, 0.f);
    }
}

// ---------------- kernel C: a2d streaming (logit base into g_P) ----------------
__global__ __launch_bounds__(128) void a2d_kernel(
    const float* __restrict__ in2d, const float* __restrict__ w2d,
    const float* __restrict__ b2d)
{
    extern __shared__ float smC[];
    float* sd = smC;
    float* sw = smC + 128 * PITCH;

    int tid = threadIdx.x;
    int n = blockIdx.y;
    int m0 = blockIdx.x * 128;

    for (int i = tid; i < H_ * C2_; i += 128)
        sw[i] = w2d[(i & 127) * H_ + (i >> 7)] * W2DS;

    const float4* g = (const float4*)(in2d + ((long)n * N_ + m0) * C2_);
    for (int i = tid; i < 128 * 32; i += 128) {
        int row = i >> 5, c4 = i & 31;
        float4 v = g[i];
        *(float4*)&sd[row * PITCH + c4 * 4] = v;
    }
    __syncthreads();

    u64 acc[12];
    #pragma unroll
    for (int h = 0; h < 12; h++) acc[h] = 0ULL;

    const ulonglong2* drow = (const ulonglong2*)(sd + tid * PITCH);
    const ulonglong2* swp  = (const ulonglong2*)sw;

    #pragma unroll 4
    for (int c4 = 0; c4 < 32; c4++) {
        ulonglong2 d = drow[c4];
        #pragma unroll
        for (int h = 0; h < 12; h++) {
            ulonglong2 w = swp[h * 32 + c4];
            fma2(acc[h], d.x, w.x);
            fma2(acc[h], d.y, w.y);
        }
    }
    #pragma unroll
    for (int h = 0; h < 12; h++) {
        float2 a = *(float2*)&acc[h];
        g_P[((long)n * H_ + h) * N_ + m0 + tid] = a.x + a.y + b2d[h] * W2DS;
    }
}

// ---------------- kernel D: qk GEMM + mask + EXP (in place) ----------------
__global__ __launch_bounds__(256) void qk_kernel(const float* __restrict__ mask)
{
    __shared__ float Aq[32][68];
    __shared__ float Bk[32][68];
    int h  = blockIdx.z;
    int nb = blockIdx.y * 64, mb = blockIdx.x * 64;
    int tid = threadIdx.x;

    for (int i = tid; i < 64 * 8; i += 256) {
        int row = i >> 3, k4 = (i & 7) * 4;
        float4 q = *(const float4*)&g_qaug[((nb + row) * H_ + h) * 32 + k4];
        Aq[k4+0][row] = q.x; Aq[k4+1][row] = q.y; Aq[k4+2][row] = q.z; Aq[k4+3][row] = q.w;
        float4 k = *(const float4*)&g_kaug[((mb + row) * H_ + h) * 32 + k4];
        Bk[k4+0][row] = k.x; Bk[k4+1][row] = k.y; Bk[k4+2][row] = k.z; Bk[k4+3][row] = k.w;
    }
    __syncthreads();

    int tx = tid & 15, ty = tid >> 4;
    float acc[4][4] = {};
    #pragma unroll
    for (int k = 0; k < 32; k++) {
        float4 a4 = *(const float4*)&Aq[k][ty * 4];
        float4 b4 = *(const float4*)&Bk[k][tx * 4];
        float a[4] = {a4.x, a4.y, a4.z, a4.w};
        float b[4] = {b4.x, b4.y, b4.z, b4.w};
        #pragma unroll
        for (int i = 0; i < 4; i++)
            #pragma unroll
            for (int j = 0; j < 4; j++)
                acc[i][j] += a[i] * b[j];
    }
    float mm[4], mn[4];
    #pragma unroll
    for (int j = 0; j < 4; j++) mm[j] = mask[mb + tx * 4 + j];
    #pragma unroll
    for (int i = 0; i < 4; i++) mn[i] = mask[nb + ty * 4 + i];

    #pragma unroll
    for (int i = 0; i < 4; i++) {
        float* p = &g_P[((long)(nb + ty * 4 + i) * H_ + h) * N_ + mb + tx * 4];
        float4 L4 = *(float4*)p;
        L4.x = __expf(L4.x + acc[i][0] - 100000.f * (1.f - mn[i] * mm[0]));
        L4.y = __expf(L4.y + acc[i][1] - 100000.f * (1.f - mn[i] * mm[1]));
        L4.z = __expf(L4.z + acc[i][2] - 100000.f * (1.f - mn[i] * mm[2]));
        L4.w = __expf(L4.w + acc[i][3] - 100000.f * (1.f - mn[i] * mm[3]));
        *(float4*)p = L4;
    }
}

// ---------------- kernel E: warp-specialized attention ----------------
// Warps 0-7:  phase3 (q = wid>>1, c-half = wid&1), 12 heads per thread
// Warps 8-11: phase2b (3 heads = 3*(wid-8)..+2, all 4 q)
// All warps:  phase2 p-production (h = wid, lane = m) + srun
__global__ void __launch_bounds__(384, 2) attn_kernel(
    const float* __restrict__ in2d,
    const float* __restrict__ rot, const float* __restrict__ trans)
{
    extern __shared__ float sm[];
    float* s2d  = sm;                      // QB*TM*PITCH = 16896
    float* spT  = sm + QB * TM * PITCH;    // [q][mi][14 u64 slots] = 3584
    float* spts = spT + QB * TM * 28;      // [q][12][24] = 1152
    float* sinv = spts + QB * H_ * 24;     // 48

    int tid  = threadIdx.x;
    int wid  = tid >> 5;
    int lane = tid & 31;
    int n0   = blockIdx.x * QB;

    bool isP3 = wid < 8;
    int q3 = wid >> 1;
    int j  = ((wid & 1) << 5) + lane;      // u64 channel index 0..63
    int hq = wid - 8;                      // 2b head group
    int hB = 3 * hq + lane / 10;           // 2b head (lane<30)
    int pB = lane % 10;                    // 2b ulonglong2 index 0..9

    unsigned s2d_sm = smem_u32(s2d);
    const float4* g2d = (const float4*)in2d;
    const ulonglong2* vmp = (const ulonglong2*)g_vm;

    u64 acc3[12];
    ulonglong2 accb[QB];
    #pragma unroll
    for (int h = 0; h < 12; h++) acc3[h] = 0ULL;
    #pragma unroll
    for (int q = 0; q < QB; q++) accb[q] = make_ulonglong2(0ULL, 0ULL);
    float srun[QB] = {};

    for (int t = 0; t < N_ / TM; t++) {
        int m0 = t * TM;

        // stage tile
        for (int i = tid; i < QB * TM * 32; i += 384) {
            int q = i >> 10, r = i & 1023;
            int mi = r >> 5, cc = r & 31;
            cpa16(s2d_sm + ((q * TM + mi) * PITCH + cc * 4) * 4,
                  &g2d[((long)(n0 + q) * N_ + m0 + mi) * 32 + cc]);
        }
        asm volatile("cp.async.commit_group;");

        // phase 2: p production (h = wid, m = lane)
        float pv[QB];
        #pragma unroll
        for (int q = 0; q < QB; q++)
            pv[q] = g_P[((long)(n0 + q) * H_ + wid) * N_ + m0 + lane];
        #pragma unroll
        for (int q = 0; q < QB; q++) {
            srun[q] += pv[q];
            *(float2*)&spT[((q * TM + lane) * 14 + wid) * 2] = make_float2(pv[q], pv[q]);
        }
        asm volatile("cp.async.wait_group 0;");
        __syncthreads();

        if (isP3) {
            const u64* drow = (const u64*)s2d;   // 66 u64 per row
            #pragma unroll 8
            for (int mi = 0; mi < TM; mi++) {
                u64 d = drow[(q3 * TM + mi) * 66 + j];
                const ulonglong2* prow = (const ulonglong2*)&spT[(q3 * TM + mi) * 28];
                #pragma unroll
                for (int ht = 0; ht < 6; ht++) {
                    ulonglong2 pp = prow[ht];
                    fma2(acc3[2 * ht],     pp.x, d);
                    fma2(acc3[2 * ht + 1], pp.y, d);
                }
            }
        } else {
            #pragma unroll 4
            for (int mi = 0; mi < TM; mi++) {
                int m = m0 + mi;
                ulonglong2 v = make_ulonglong2(0ULL, 0ULL);
                if (lane < 30)
                    v = vmp[((long)m * H_ + hB) * 16 + pB];
                const u64* prow = (const u64*)&spT[(0 * TM + mi) * 28];  // per-q below
                #pragma unroll
                for (int q = 0; q < QB; q++) {
                    u64 p = *(const u64*)&spT[((q * TM + mi) * 14 + hB) * 2];
                    fma2(accb[q].x, p, v.x);
                    fma2(accb[q].y, p, v.y);
                }
                (void)prow;
            }
        }
        __syncthreads();
    }

    // ---- epilogue ----
    // row sums (all warps, h = wid)
    #pragma unroll
    for (int q = 0; q < QB; q++) {
        float s = srun[q];
        #pragma unroll
        for (int o = 16; o > 0; o >>= 1)
            s += __shfl_xor_sync(0xffffffffu, s, o);
        if (lane == 0) sinv[q * H_ + wid] = 1.f / s;
    }
    __syncthreads();

    if (isP3) {
        // attn_2d: normalize + write (no m-split reduction needed)
        #pragma unroll
        for (int h = 0; h < 12; h++) {
            u64 iv2 = pack2(sinv[q3 * H_ + h]);
            u64 a = acc3[h];
            mul2(a, iv2);
            *(float2*)&g_feat[(long)(n0 + q3) * NFEAT + 576 + h * 128 + 2 * j] =
                *(float2*)&a;
        }
    } else if (lane < 30) {
        // res_scalar (pB<4) / res_point (4<=pB<10)
        #pragma unroll
        for (int q = 0; q < QB; q++) {
            u64 iv2 = pack2(sinv[q * H_ + hB]);
            u64 vx = accb[q].x, vy = accb[q].y;
            mul2(vx, iv2); mul2(vy, iv2);
            float2 lo = *(float2*)&vx;
            float2 hi = *(float2*)&vy;
            float4 r = make_float4(lo.x, lo.y, hi.x, hi.y);
            if (pB < 4)
                *(float4*)&g_feat[(long)(n0 + q) * NFEAT + hB * 16 + 4 * pB] = r;
            else
                *(float4*)&spts[(q * H_ + hB) * 24 + 4 * (pB - 4)] = r;
        }
    }
    __syncthreads();

    // point transform: warp h = wid, lane < 8
    if (lane < 8) {
        #pragma unroll
        for (int q = 0; q < QB; q++) {
            int n = n0 + q;
            float* f = g_feat + (long)n * NFEAT;
            int p = lane;
            float gx = spts[(q * H_ + wid) * 24 + p * 3 + 0] - trans[n * 3 + 0];
            float gy = spts[(q * H_ + wid) * 24 + p * 3 + 1] - trans[n * 3 + 1];
            float gz = spts[(q * H_ + wid) * 24 + p * 3 + 2] - trans[n * 3 + 2];
            float lx = rot[n*9+0]*gx + rot[n*9+3]*gy + rot[n*9+6]*gz;
            float ly = rot[n*9+1]*gx + rot[n*9+4]*gy + rot[n*9+7]*gz;
            float lz = rot[n*9+2]*gx + rot[n*9+5]*gy + rot[n*9+8]*gz;
            float d  = sqrtf(1e-8f + lx*lx + ly*ly + lz*lz);
            f[192 + wid * 8 + p] = lx;
            f[288 + wid * 8 + p] = ly;
            f[384 + wid * 8 + p] = lz;
            f[480 + wid * 8 + p] = d;
        }
    }
}

// ---------------- kernel F: output GEMM ----------------
__global__ __launch_bounds__(1024) void out_gemm_kernel(
    const float* __restrict__ B, const float* __restrict__ bias,
    float* __restrict__ C)
{
    __shared__ float As[4][16][64];
    __shared__ float Bs[4][16][36];
    int tid = threadIdx.x;
    int g = tid >> 8;
    int t = tid & 255;
    int bm = blockIdx.x * 64, bn = blockIdx.y * 32;
    int tx = t & 15, ty = t >> 4;
    int lm = t >> 2, lk4 = (t & 3) * 4;
    u64 acc[4] = {0,0,0,0};

    int kbase = g * 528;
    for (int kk0 = 0; kk0 < 528; kk0 += 16) {
        int k0 = kbase + kk0;
        float4 av = *(const float4*)&g_feat[(long)(bm + lm) * NFEAT + k0 + lk4];
        As[g][lk4+0][lm] = av.x; As[g][lk4+1][lm] = av.y;
        As[g][lk4+2][lm] = av.z; As[g][lk4+3][lm] = av.w;
        if (t < 128) {
            int bk = t >> 3, bn4 = (t & 7) * 4;
            float4 bv = *(const float4*)&B[(long)(k0 + bk) * COUT_ + bn + bn4];
            *(float4*)&Bs[g][bk][bn4] = bv;
        }
        __syncthreads();
        #pragma unroll
        for (int kk = 0; kk < 16; kk++) {
            float4 a4 = *(const float4*)&As[g][kk][ty * 4];
            u64 b = *(const u64*)&Bs[g][kk][tx * 2];
            fma2(acc[0], pack2(a4.x), b);
            fma2(acc[1], pack2(a4.y), b);
            fma2(acc[2], pack2(a4.z), b);
            fma2(acc[3], pack2(a4.w), b);
        }
        __syncthreads();
    }

    float* red = &As[0][0][0];
    #pragma unroll
    for (int r = 0; r < 2; r++) {
        __syncthreads();
        if (g > 0) {
            float2 p0 = *(float2*)&acc[r * 2];
            float2 p1 = *(float2*)&acc[r * 2 + 1];
            *(float4*)&red[((g - 1) * 256 + t) * 4] = make_float4(p0.x, p0.y, p1.x, p1.y);
        }
        __syncthreads();
        if (g == 0) {
            #pragma unroll
            for (int gg = 0; gg < 3; gg++) {
                float4 v = *(float4*)&red[(gg * 256 + t) * 4];
                float2 p0 = *(float2*)&acc[r * 2];
                float2 p1 = *(float2*)&acc[r * 2 + 1];
                p0.x += v.x; p0.y += v.y; p1.x += v.z; p1.y += v.w;
                *(float2*)&acc[r * 2]     = p0;
                *(float2*)&acc[r * 2 + 1] = p1;
            }
        }
    }
    if (g == 0) {
        float b0 = bias[bn + tx * 2], b1 = bias[bn + tx * 2 + 1];
        #pragma unroll
        for (int i = 0; i < 4; i++) {
            float2 v = *(float2*)&acc[i];
            v.x += b0; v.y += b1;
            *(float2*)&C[(long)(bm + ty * 4 + i) * COUT_ + bn + tx * 2] = v;
        }
    }
}

// ---------------- launch ----------------
extern "C" void kernel_launch(void* const* d_in, const int* in_sizes, int n_in,
                              void* d_out, int out_size)
{
    const float* inputs_1d = (const float*)d_in[0];
    const float* inputs_2d = (const float*)d_in[1];
    const float* mask      = (const float*)d_in[2];
    const float* rot       = (const float*)d_in[3];
    const float* trans     = (const float*)d_in[4];
    const float* wq        = (const float*)d_in[5];
    const float* bq        = (const float*)d_in[6];
    const float* wkv       = (const float*)d_in[7];
    const float* bkv       = (const float*)d_in[8];
    const float* wqp       = (const float*)d_in[9];
    const float* bqp       = (const float*)d_in[10];
    const float* wkvp      = (const float*)d_in[11];
    const float* bkvp      = (const float*)d_in[12];
    const float* w2d       = (const float*)d_in[13];
    const float* b2d       = (const float*)d_in[14];
    const float* tpw       = (const float*)d_in[15];
    const float* wout      = (const float*)d_in[16];
    const float* bout      = (const float*)d_in[17];
    float* out = (float*)d_out;

    proj_gemm_kernel<<<dim3(16, 18), 256>>>(inputs_1d, wq, bq, wkv, bkv,
                                            wqp, bqp, wkvp, bkvp);
    transform_kernel<<<N_, 192>>>(rot, trans, tpw);

    int smemC = (128 * PITCH + H_ * C2_) * (int)sizeof(float);
    cudaFuncSetAttribute(a2d_kernel, cudaFuncAttributeMaxDynamicSharedMemorySize, smemC);
    a2d_kernel<<<dim3(8, N_), 128, smemC>>>(inputs_2d, w2d, b2d);

    qk_kernel<<<dim3(16, 16, 12), 256>>>(mask);

    int smemE = (QB * TM * PITCH + QB * TM * 28 + QB * H_ * 24 + QB * H_) * (int)sizeof(float);
    cudaFuncSetAttribute(attn_kernel, cudaFuncAttributeMaxDynamicSharedMemorySize, smemE);
    attn_kernel<<<N_ / QB, 384, smemE>>>(inputs_2d, rot, trans);

    out_gemm_kernel<<<dim3(16, 12), 1024>>>(wout, bout, out);
}

// round 10
// speedup vs baseline: 1.4090x; 1.4090x over previous
#include <cuda_runtime.h>
#include <math.h>

#define N_    1024
#define H_    12
#define C1_   384
#define C2_   128
#define COUT_ 384
#define NPROJ 1152
#define NFEAT 2112
#define QB    4
#define TM    32
#define PITCH 132

#define W2DS 0.5773502691896258f
#define SCW  0.14433756729740643f
#define PTW  0.1360827634879543f

typedef unsigned long long u64;

__device__ __forceinline__ void fma2(u64& acc, u64 a, u64 b) {
    asm("fma.rn.f32x2 %0, %1, %2, %0;" : "+l"(acc) : "l"(a), "l"(b));
}
__device__ __forceinline__ void mul2(u64& a, u64 b) {
    asm("mul.rn.f32x2 %0, %0, %1;" : "+l"(a) : "l"(b));
}
__device__ __forceinline__ u64 pack2(float a) {
    u64 r;
    asm("mov.b64 %0, {%1, %1};" : "=l"(r) : "f"(a));
    return r;
}
__device__ __forceinline__ unsigned smem_u32(const void* p) {
    return (unsigned)__cvta_generic_to_shared(p);
}
__device__ __forceinline__ void cpa16(unsigned dst, const void* src) {
    asm volatile("cp.async.cg.shared.global [%0], [%1], 16;" :: "r"(dst), "l"(src));
}

// ---------------- scratch ----------------
__device__ float g_proj [N_ * NPROJ];
__device__ float g_qpt  [N_ * 144];
__device__ float g_kpt  [N_ * 144];
__device__ float g_vpt  [N_ * 288];
__device__ float g_qaug [N_ * H_ * 32];
__device__ float g_kaug [N_ * H_ * 32];
__device__ float g_P    [(long)N_ * H_ * 1024];   // unnormalized probs
__device__ float g_iv   [N_ * H_];
__device__ float g_vm   [(long)N_ * H_ * 64];     // merged v (32 u64/row, 20 used)
__device__ float g_feat [(long)N_ * NFEAT];

// ---------------- kernel A: fused projection GEMM ----------------
__global__ __launch_bounds__(256) void proj_gemm_kernel(
    const float* __restrict__ A,
    const float* __restrict__ wq,  const float* __restrict__ bq,
    const float* __restrict__ wkv, const float* __restrict__ bkv,
    const float* __restrict__ wqp, const float* __restrict__ bqp,
    const float* __restrict__ wkvp,const float* __restrict__ bkvp)
{
    __shared__ float As[16][64];
    __shared__ float Bs[16][68];
    int bm = blockIdx.x * 64, bn = blockIdx.y * 64;
    int tid = threadIdx.x;
    int tx = tid & 15, ty = tid >> 4;
    int lm = tid >> 2, lk4 = (tid & 3) * 4;
    int bk = tid >> 4, bn4 = (tid & 15) * 4;
    u64 acc01[4] = {0,0,0,0}, acc23[4] = {0,0,0,0};

    for (int k0 = 0; k0 < C1_; k0 += 16) {
        float4 av = *(const float4*)&A[(bm + lm) * C1_ + k0 + lk4];
        As[lk4+0][lm] = av.x; As[lk4+1][lm] = av.y;
        As[lk4+2][lm] = av.z; As[lk4+3][lm] = av.w;
        int kg = k0 + bk;
        #pragma unroll
        for (int jj = 0; jj < 4; jj++) {
            int j = bn + bn4 + jj;
            float v;
            if      (j < 192) v = wq  [kg * 192 + j];
            else if (j < 576) v = wkv [kg * 384 + (j - 192)];
            else if (j < 720) v = wqp [kg * 144 + (j - 576)];
            else              v = wkvp[kg * 432 + (j - 720)];
            Bs[bk][bn4 + jj] = v;
        }
        __syncthreads();
        #pragma unroll
        for (int kk = 0; kk < 16; kk++) {
            float4 a4 = *(const float4*)&As[kk][ty * 4];
            ulonglong2 b2 = *(const ulonglong2*)&Bs[kk][tx * 4];
            float a[4] = {a4.x, a4.y, a4.z, a4.w};
            #pragma unroll
            for (int i = 0; i < 4; i++) {
                u64 ai = pack2(a[i]);
                fma2(acc01[i], ai, b2.x);
                fma2(acc23[i], ai, b2.y);
            }
        }
        __syncthreads();
    }
    #pragma unroll
    for (int i = 0; i < 4; i++) {
        float2 lo = *(float2*)&acc01[i];
        float2 hi = *(float2*)&acc23[i];
        float accv[4] = {lo.x, lo.y, hi.x, hi.y};
        #pragma unroll
        for (int j = 0; j < 4; j++) {
            int jg = bn + tx * 4 + j;
            float bias;
            if      (jg < 192) bias = bq  [jg];
            else if (jg < 576) bias = bkv [jg - 192];
            else if (jg < 720) bias = bqp [jg - 576];
            else               bias = bkvp[jg - 720];
            g_proj[(bm + ty * 4 + i) * NPROJ + jg] = accv[j] + bias;
        }
    }
}

// ---------------- kernel B: transform + aug vectors + merged v ----------------
__global__ __launch_bounds__(192) void transform_kernel(
    const float* __restrict__ rot, const float* __restrict__ trans,
    const float* __restrict__ tpw)
{
    int n = blockIdx.x;
    int tid = threadIdx.x;
    __shared__ float sn2[192];

    const float* pr = g_proj + n * NPROJ;
    float r00 = rot[n*9+0], r01 = rot[n*9+1], r02 = rot[n*9+2];
    float r10 = rot[n*9+3], r11 = rot[n*9+4], r12 = rot[n*9+5];
    float r20 = rot[n*9+6], r21 = rot[n*9+7], r22 = rot[n*9+8];
    float t0 = trans[n*3+0], t1 = trans[n*3+1], t2 = trans[n*3+2];

    float nrm = 0.f;
    if (tid < 48) {
        int pp = tid;
        float px = pr[576 +       pp];
        float py = pr[576 +  48 + pp];
        float pz = pr[576 +  96 + pp];
        float gx = r00*px + r01*py + r02*pz + t0;
        float gy = r10*px + r11*py + r12*pz + t1;
        float gz = r20*px + r21*py + r22*pz + t2;
        int h = pp >> 2, p = pp & 3;
        float* o = g_qpt + n * 144 + h * 12 + p * 3;
        o[0] = gx; o[1] = gy; o[2] = gz;
        nrm = gx*gx + gy*gy + gz*gz;
    } else {
        int pp = tid - 48;
        float px = pr[720 +       pp];
        float py = pr[720 + 144 + pp];
        float pz = pr[720 + 288 + pp];
        float gx = r00*px + r01*py + r02*pz + t0;
        float gy = r10*px + r11*py + r12*pz + t1;
        float gz = r20*px + r21*py + r22*pz + t2;
        int h = pp / 12, r = pp % 12;
        if (r < 4) {
            float* o = g_kpt + n * 144 + h * 12 + r * 3;
            o[0] = gx; o[1] = gy; o[2] = gz;
            nrm = gx*gx + gy*gy + gz*gz;
        } else {
            float* o = g_vpt + n * 288 + h * 24 + (r - 4) * 3;
            o[0] = gx; o[1] = gy; o[2] = gz;
        }
    }
    sn2[tid] = nrm;
    __syncthreads();
    if (tid < H_) {
        int h = tid;
        float q2 = 0.f, k2 = 0.f;
        #pragma unroll
        for (int p = 0; p < 4; p++) q2 += sn2[h * 4 + p];
        #pragma unroll
        for (int r = 0; r < 4; r++) k2 += sn2[48 + h * 12 + r];

        float tp = tpw[h];
        float spv = tp > 20.f ? tp : log1pf(__expf(tp));
        float pw = PTW * spv;

        float* qa = g_qaug + (n * H_ + h) * 32;
        float* ka = g_kaug + (n * H_ + h) * 32;
        #pragma unroll
        for (int c = 0; c < 16; c++) {
            qa[c] = SCW * pr[h * 16 + c];
            ka[c] = pr[192 + h * 32 + c];
        }
        #pragma unroll
        for (int c = 0; c < 12; c++) {
            qa[16 + c] = pw * g_qpt[n * 144 + h * 12 + c];
            ka[16 + c] = g_kpt[n * 144 + h * 12 + c];
        }
        qa[28] = -0.5f * pw * q2; qa[29] = 1.f; qa[30] = 0.f; qa[31] = 0.f;
        ka[28] = 1.f; ka[29] = -0.5f * pw * k2; ka[30] = 0.f; ka[31] = 0.f;

        // merged v: u64 j<8 -> vs pairs, 8<=j<20 -> vp pairs, rest 0
        float2* vm = (float2*)&g_vm[((long)n * H_ + h) * 64];
        #pragma unroll
        for (int j = 0; j < 8; j++)
            vm[j] = make_float2(pr[192 + h * 32 + 16 + 2*j],
                                pr[192 + h * 32 + 16 + 2*j + 1]);
        #pragma unroll
        for (int j = 8; j < 20; j++)
            vm[j] = make_float2(g_vpt[n * 288 + h * 24 + 2*(j-8)],
                                g_vpt[n * 288 + h * 24 + 2*(j-8) + 1]);
        #pragma unroll
        for (int j = 20; j < 32; j++)
            vm[j] = make_float2(0.f, 0.f);
    }
}

// ---------------- kernel C: a2d streaming (logit base into g_P) ----------------
__global__ __launch_bounds__(128) void a2d_kernel(
    const float* __restrict__ in2d, const float* __restrict__ w2d,
    const float* __restrict__ b2d)
{
    extern __shared__ float smC[];
    float* sd = smC;
    float* sw = smC + 128 * PITCH;

    int tid = threadIdx.x;
    int n = blockIdx.y;
    int m0 = blockIdx.x * 128;

    for (int i = tid; i < H_ * C2_; i += 128)
        sw[i] = w2d[(i & 127) * H_ + (i >> 7)] * W2DS;

    const float4* g = (const float4*)(in2d + ((long)n * N_ + m0) * C2_);
    for (int i = tid; i < 128 * 32; i += 128) {
        int row = i >> 5, c4 = i & 31;
        float4 v = g[i];
        *(float4*)&sd[row * PITCH + c4 * 4] = v;
    }
    __syncthreads();

    u64 acc[12];
    #pragma unroll
    for (int h = 0; h < 12; h++) acc[h] = 0ULL;

    const ulonglong2* drow = (const ulonglong2*)(sd + tid * PITCH);
    const ulonglong2* swp  = (const ulonglong2*)sw;

    #pragma unroll 4
    for (int c4 = 0; c4 < 32; c4++) {
        ulonglong2 d = drow[c4];
        #pragma unroll
        for (int h = 0; h < 12; h++) {
            ulonglong2 w = swp[h * 32 + c4];
            fma2(acc[h], d.x, w.x);
            fma2(acc[h], d.y, w.y);
        }
    }
    #pragma unroll
    for (int h = 0; h < 12; h++) {
        float2 a = *(float2*)&acc[h];
        g_P[((long)n * H_ + h) * N_ + m0 + tid] = a.x + a.y + b2d[h] * W2DS;
    }
}

// ---------------- kernel D: qk GEMM + mask + EXP (in place) ----------------
__global__ __launch_bounds__(256) void qk_kernel(const float* __restrict__ mask)
{
    __shared__ float Aq[32][68];
    __shared__ float Bk[32][68];
    int h  = blockIdx.z;
    int nb = blockIdx.y * 64, mb = blockIdx.x * 64;
    int tid = threadIdx.x;

    for (int i = tid; i < 64 * 8; i += 256) {
        int row = i >> 3, k4 = (i & 7) * 4;
        float4 q = *(const float4*)&g_qaug[((nb + row) * H_ + h) * 32 + k4];
        Aq[k4+0][row] = q.x; Aq[k4+1][row] = q.y; Aq[k4+2][row] = q.z; Aq[k4+3][row] = q.w;
        float4 k = *(const float4*)&g_kaug[((mb + row) * H_ + h) * 32 + k4];
        Bk[k4+0][row] = k.x; Bk[k4+1][row] = k.y; Bk[k4+2][row] = k.z; Bk[k4+3][row] = k.w;
    }
    __syncthreads();

    int tx = tid & 15, ty = tid >> 4;
    float acc[4][4] = {};
    #pragma unroll
    for (int k = 0; k < 32; k++) {
        float4 a4 = *(const float4*)&Aq[k][ty * 4];
        float4 b4 = *(const float4*)&Bk[k][tx * 4];
        float a[4] = {a4.x, a4.y, a4.z, a4.w};
        float b[4] = {b4.x, b4.y, b4.z, b4.w};
        #pragma unroll
        for (int i = 0; i < 4; i++)
            #pragma unroll
            for (int j = 0; j < 4; j++)
                acc[i][j] += a[i] * b[j];
    }
    float mm[4], mn[4];
    #pragma unroll
    for (int j = 0; j < 4; j++) mm[j] = mask[mb + tx * 4 + j];
    #pragma unroll
    for (int i = 0; i < 4; i++) mn[i] = mask[nb + ty * 4 + i];

    #pragma unroll
    for (int i = 0; i < 4; i++) {
        float* p = &g_P[((long)(nb + ty * 4 + i) * H_ + h) * N_ + mb + tx * 4];
        float4 L4 = *(float4*)p;
        L4.x = __expf(L4.x + acc[i][0] - 100000.f * (1.f - mn[i] * mm[0]));
        L4.y = __expf(L4.y + acc[i][1] - 100000.f * (1.f - mn[i] * mm[1]));
        L4.z = __expf(L4.z + acc[i][2] - 100000.f * (1.f - mn[i] * mm[2]));
        L4.w = __expf(L4.w + acc[i][3] - 100000.f * (1.f - mn[i] * mm[3]));
        *(float4*)p = L4;
    }
}

// ---------------- kernel D2: 1/rowsum ----------------
__global__ __launch_bounds__(256) void stats_kernel()
{
    int row  = blockIdx.x * 8 + (threadIdx.x >> 5);
    int lane = threadIdx.x & 31;
    const float4* Pr = (const float4*)(g_P + (long)row * N_);
    float s = 0.f;
    #pragma unroll
    for (int j = 0; j < 8; j++) {
        float4 v = Pr[j * 32 + lane];
        s += v.x + v.y + v.z + v.w;
    }
    #pragma unroll
    for (int o = 16; o > 0; o >>= 1)
        s += __shfl_xor_sync(0xffffffffu, s, o);
    if (lane == 0) g_iv[row] = 1.f / s;
}

// ---------------- kernel E: attention accumulation ----------------
// p layout: spH[h][mi][(p,p) x 4 q] = 8 floats per (h,mi), 32B aligned.
__global__ void __launch_bounds__(384, 2) attn_kernel(
    const float* __restrict__ in2d,
    const float* __restrict__ rot, const float* __restrict__ trans)
{
    extern __shared__ float sm[];
    float* s2d  = sm;                       // 16896
    float* spH  = sm + QB * TM * PITCH;     // 12*32*8 = 3072
    float* sinv = spH + H_ * TM * 8;        // 48

    int tid  = threadIdx.x;
    int h    = tid >> 5;
    int lane = tid & 31;
    int n0   = blockIdx.x * QB;

    int c4 = tid & 31;
    int hp = (tid >> 5) % 6;
    int mq = tid / 192;
    int h0 = hp * 2;

    unsigned s2d_sm = smem_u32(s2d);
    const float4* g2d = (const float4*)in2d;
    const u64* vm64 = (const u64*)g_vm;
    const ulonglong2* pbase = (const ulonglong2*)spH;  // [h*32+mi][2] ul2 = q-pairs

    ulonglong2 a2[2][QB];
    #pragma unroll
    for (int hh = 0; hh < 2; hh++)
        #pragma unroll
        for (int q = 0; q < QB; q++) a2[hh][q] = make_ulonglong2(0ULL, 0ULL);
    u64 acc2b[QB] = {0,0,0,0};

    for (int t = 0; t < N_ / TM; t++) {
        int m0 = t * TM;
        int m = m0 + lane;

        // stage tile (cp.async)
        for (int i = tid; i < QB * TM * 32; i += 384) {
            int q = i >> 10, r = i & 1023;
            int mi = r >> 5, cc = r & 31;
            cpa16(s2d_sm + ((q * TM + mi) * PITCH + cc * 4) * 4,
                  &g2d[((long)(n0 + q) * N_ + m0 + mi) * 32 + cc]);
        }
        asm volatile("cp.async.commit_group;");

        // phase 2: p production (h = warp, m = lane)
        float pv[QB];
        #pragma unroll
        for (int q = 0; q < QB; q++)
            pv[q] = g_P[((long)(n0 + q) * H_ + h) * N_ + m];

        asm volatile("cp.async.wait_group 0;");
        {
            float* dst = &spH[(h * 32 + lane) * 8];
            *(float4*)dst       = make_float4(pv[0], pv[0], pv[1], pv[1]);
            *(float4*)(dst + 4) = make_float4(pv[2], pv[2], pv[3], pv[3]);
        }
        __syncthreads();

        // phase 3: attn_2d (2 heads/thread, m-split; p via LDS.128 broadcasts)
        {
            const ulonglong2* s2d8 = (const ulonglong2*)s2d;
            int mbeg = mq * 16;
            #pragma unroll 4
            for (int mi = mbeg; mi < mbeg + 16; mi++) {
                ulonglong2 pA0 = pbase[(h0 * 32 + mi) * 2 + 0];        // h0: q0,q1
                ulonglong2 pA1 = pbase[(h0 * 32 + mi) * 2 + 1];        // h0: q2,q3
                ulonglong2 pB0 = pbase[((h0 + 1) * 32 + mi) * 2 + 0];  // h1: q0,q1
                ulonglong2 pB1 = pbase[((h0 + 1) * 32 + mi) * 2 + 1];  // h1: q2,q3
                u64 pH0[4] = {pA0.x, pA0.y, pA1.x, pA1.y};
                u64 pH1[4] = {pB0.x, pB0.y, pB1.x, pB1.y};
                #pragma unroll
                for (int q = 0; q < QB; q++) {
                    ulonglong2 d = s2d8[(q * TM + mi) * 33 + c4];
                    fma2(a2[0][q].x, pH0[q], d.x);
                    fma2(a2[0][q].y, pH0[q], d.y);
                    fma2(a2[1][q].x, pH1[q], d.x);
                    fma2(a2[1][q].y, pH1[q], d.y);
                }
            }
        }

        // phase 2b: merged-v accumulation (lane = u64 channel pair)
        {
            const u64* vrow = vm64 + ((long)m0 * H_ + h) * 32 + lane;
            #pragma unroll 8
            for (int mi = 0; mi < TM; mi++) {
                u64 v = vrow[(long)mi * H_ * 32];
                ulonglong2 pq01 = pbase[(h * 32 + mi) * 2 + 0];
                ulonglong2 pq23 = pbase[(h * 32 + mi) * 2 + 1];
                fma2(acc2b[0], pq01.x, v);
                fma2(acc2b[1], pq01.y, v);
                fma2(acc2b[2], pq23.x, v);
                fma2(acc2b[3], pq23.y, v);
            }
        }
        __syncthreads();
    }

    // ---- epilogue ----
    float inv[QB];
    #pragma unroll
    for (int q = 0; q < QB; q++) {
        inv[q] = g_iv[(n0 + q) * H_ + h];
        if (lane == 0) sinv[q * H_ + h] = inv[q];
    }
    #pragma unroll
    for (int q = 0; q < QB; q++) {
        int n = n0 + q;
        float* f = g_feat + (long)n * NFEAT;
        float2 ac = *(float2*)&acc2b[q];
        ac.x *= inv[q]; ac.y *= inv[q];
        if (lane < 8) {               // res_scalar ch 2l, 2l+1
            f[h * 16 + 2 * lane]     = ac.x;
            f[h * 16 + 2 * lane + 1] = ac.y;
        }
        __syncwarp();
        if (lane >= 8 && lane < 20) { // res_point ch 2(l-8), +1 -> smem
            spH[h * 64 + 2 * (lane - 8)]     = ac.x;
            spH[h * 64 + 2 * (lane - 8) + 1] = ac.y;
        }
        __syncwarp();
        if (lane < 8) {
            int p = lane;
            float gx = spH[h * 64 + p * 3 + 0] - trans[n * 3 + 0];
            float gy = spH[h * 64 + p * 3 + 1] - trans[n * 3 + 1];
            float gz = spH[h * 64 + p * 3 + 2] - trans[n * 3 + 2];
            float lx = rot[n*9+0]*gx + rot[n*9+3]*gy + rot[n*9+6]*gz;
            float ly = rot[n*9+1]*gx + rot[n*9+4]*gy + rot[n*9+7]*gz;
            float lz = rot[n*9+2]*gx + rot[n*9+5]*gy + rot[n*9+8]*gz;
            float d  = sqrtf(1e-8f + lx*lx + ly*ly + lz*lz);
            f[192 + h * 8 + p] = lx;
            f[288 + h * 8 + p] = ly;
            f[384 + h * 8 + p] = lz;
            f[480 + h * 8 + p] = d;
        }
        __syncwarp();
    }
    __syncthreads();

    float4* red = (float4*)s2d;
    #pragma unroll
    for (int hh = 0; hh < 2; hh++) {
        __syncthreads();
        #pragma unroll
        for (int q = 0; q < QB; q++) {
            u64 iv2 = pack2(sinv[q * H_ + h0 + hh]);
            u64 vx = a2[hh][q].x, vy = a2[hh][q].y;
            mul2(vx, iv2); mul2(vy, iv2);
            float2 lo = *(float2*)&vx;
            float2 hi = *(float2*)&vy;
            red[(q * 2 + mq) * 192 + hp * 32 + c4] = make_float4(lo.x, lo.y, hi.x, hi.y);
        }
        __syncthreads();
        if (mq == 0) {
            #pragma unroll
            for (int q = 0; q < QB; q++) {
                float4 a = red[(q * 2    ) * 192 + hp * 32 + c4];
                float4 b = red[(q * 2 + 1) * 192 + hp * 32 + c4];
                a.x += b.x; a.y += b.y; a.z += b.z; a.w += b.w;
                *(float4*)&g_feat[(long)(n0 + q) * NFEAT + 576 + (h0 + hh) * 128 + c4 * 4] = a;
            }
        }
    }
}

// ---------------- kernel F: output GEMM ----------------
__global__ __launch_bounds__(1024) void out_gemm_kernel(
    const float* __restrict__ B, const float* __restrict__ bias,
    float* __restrict__ C)
{
    __shared__ float As[4][16][64];
    __shared__ float Bs[4][16][36];
    int tid = threadIdx.x;
    int g = tid >> 8;
    int t = tid & 255;
    int bm = blockIdx.x * 64, bn = blockIdx.y * 32;
    int tx = t & 15, ty = t >> 4;
    int lm = t >> 2, lk4 = (t & 3) * 4;
    u64 acc[4] = {0,0,0,0};

    int kbase = g * 528;
    for (int kk0 = 0; kk0 < 528; kk0 += 16) {
        int k0 = kbase + kk0;
        float4 av = *(const float4*)&g_feat[(long)(bm + lm) * NFEAT + k0 + lk4];
        As[g][lk4+0][lm] = av.x; As[g][lk4+1][lm] = av.y;
        As[g][lk4+2][lm] = av.z; As[g][lk4+3][lm] = av.w;
        if (t < 128) {
            int bk = t >> 3, bn4 = (t & 7) * 4;
            float4 bv = *(const float4*)&B[(long)(k0 + bk) * COUT_ + bn + bn4];
            *(float4*)&Bs[g][bk][bn4] = bv;
        }
        __syncthreads();
        #pragma unroll
        for (int kk = 0; kk < 16; kk++) {
            float4 a4 = *(const float4*)&As[g][kk][ty * 4];
            u64 b = *(const u64*)&Bs[g][kk][tx * 2];
            fma2(acc[0], pack2(a4.x), b);
            fma2(acc[1], pack2(a4.y), b);
            fma2(acc[2], pack2(a4.z), b);
            fma2(acc[3], pack2(a4.w), b);
        }
        __syncthreads();
    }

    float* red = &As[0][0][0];
    #pragma unroll
    for (int r = 0; r < 2; r++) {
        __syncthreads();
        if (g > 0) {
            float2 p0 = *(float2*)&acc[r * 2];
            float2 p1 = *(float2*)&acc[r * 2 + 1];
            *(float4*)&red[((g - 1) * 256 + t) * 4] = make_float4(p0.x, p0.y, p1.x, p1.y);
        }
        __syncthreads();
        if (g == 0) {
            #pragma unroll
            for (int gg = 0; gg < 3; gg++) {
                float4 v = *(float4*)&red[(gg * 256 + t) * 4];
                float2 p0 = *(float2*)&acc[r * 2];
                float2 p1 = *(float2*)&acc[r * 2 + 1];
                p0.x += v.x; p0.y += v.y; p1.x += v.z; p1.y += v.w;
                *(float2*)&acc[r * 2]     = p0;
                *(float2*)&acc[r * 2 + 1] = p1;
            }
        }
    }
    if (g == 0) {
        float b0 = bias[bn + tx * 2], b1 = bias[bn + tx * 2 + 1];
        #pragma unroll
        for (int i = 0; i < 4; i++) {
            float2 v = *(float2*)&acc[i];
            v.x += b0; v.y += b1;
            *(float2*)&C[(long)(bm + ty * 4 + i) * COUT_ + bn + tx * 2] = v;
        }
    }
}

// ---------------- launch ----------------
extern "C" void kernel_launch(void* const* d_in, const int* in_sizes, int n_in,
                              void* d_out, int out_size)
{
    const float* inputs_1d = (const float*)d_in[0];
    const float* inputs_2d = (const float*)d_in[1];
    const float* mask      = (const float*)d_in[2];
    const float* rot       = (const float*)d_in[3];
    const float* trans     = (const float*)d_in[4];
    const float* wq        = (const float*)d_in[5];
    const float* bq        = (const float*)d_in[6];
    const float* wkv       = (const float*)d_in[7];
    const float* bkv       = (const float*)d_in[8];
    const float* wqp       = (const float*)d_in[9];
    const float* bqp       = (const float*)d_in[10];
    const float* wkvp      = (const float*)d_in[11];
    const float* bkvp      = (const float*)d_in[12];
    const float* w2d       = (const float*)d_in[13];
    const float* b2d       = (const float*)d_in[14];
    const float* tpw       = (const float*)d_in[15];
    const float* wout      = (const float*)d_in[16];
    const float* bout      = (const float*)d_in[17];
    float* out = (float*)d_out;

    proj_gemm_kernel<<<dim3(16, 18), 256>>>(inputs_1d, wq, bq, wkv, bkv,
                                            wqp, bqp, wkvp, bkvp);
    transform_kernel<<<N_, 192>>>(rot, trans, tpw);

    int smemC = (128 * PITCH + H_ * C2_) * (int)sizeof(float);
    cudaFuncSetAttribute(a2d_kernel, cudaFuncAttributeMaxDynamicSharedMemorySize, smemC);
    a2d_kernel<<<dim3(8, N_), 128, smemC>>>(inputs_2d, w2d, b2d);

    qk_kernel<<<dim3(16, 16, 12), 256>>>(mask);
    stats_kernel<<<(N_ * H_) / 8, 256>>>();

    int smemE = (QB * TM * PITCH + H_ * TM * 8 + QB * H_) * (int)sizeof(float);
    cudaFuncSetAttribute(attn_kernel, cudaFuncAttributeMaxDynamicSharedMemorySize, smemE);
    attn_kernel<<<N_ / QB, 384, smemE>>>(inputs_2d, rot, trans);

    out_gemm_kernel<<<dim3(16, 12), 1024>>>(wout, bout, out);
}

// round 11
// speedup vs baseline: 1.4605x; 1.0365x over previous
#include <cuda_runtime.h>
#include <math.h>

#define N_    1024
#define H_    12
#define C1_   384
#define C2_   128
#define COUT_ 384
#define NPROJ 1152
#define NFEAT 2112
#define QB    4
#define TM    16
#define NT    (N_ / TM)            // 64 tiles
#define BUFF  (QB * TM * C2_)      // 8192 floats = 32KB per buffer
#define PITCH 132

#define W2DS 0.5773502691896258f
#define SCW  0.14433756729740643f
#define PTW  0.1360827634879543f

typedef unsigned long long u64;

__device__ __forceinline__ void fma2(u64& acc, u64 a, u64 b) {
    asm("fma.rn.f32x2 %0, %1, %2, %0;" : "+l"(acc) : "l"(a), "l"(b));
}
__device__ __forceinline__ void mul2(u64& a, u64 b) {
    asm("mul.rn.f32x2 %0, %0, %1;" : "+l"(a) : "l"(b));
}
__device__ __forceinline__ u64 pack2(float a) {
    u64 r;
    asm("mov.b64 %0, {%1, %1};" : "=l"(r) : "f"(a));
    return r;
}
__device__ __forceinline__ unsigned smem_u32(const void* p) {
    return (unsigned)__cvta_generic_to_shared(p);
}
__device__ __forceinline__ void bulk_cp(unsigned dst, const void* src,
                                        unsigned bytes, unsigned mbar) {
    asm volatile(
        "cp.async.bulk.shared::cta.global.mbarrier::complete_tx::bytes "
        "[%0], [%1], %2, [%3];"
        :: "r"(dst), "l"(src), "r"(bytes), "r"(mbar) : "memory");
}
__device__ __forceinline__ void mbar_init(unsigned mbar, unsigned cnt) {
    asm volatile("mbarrier.init.shared.b64 [%0], %1;" :: "r"(mbar), "r"(cnt) : "memory");
}
__device__ __forceinline__ void mbar_expect_tx(unsigned mbar, unsigned bytes) {
    asm volatile("mbarrier.arrive.expect_tx.shared.b64 _, [%0], %1;"
                 :: "r"(mbar), "r"(bytes) : "memory");
}
__device__ __forceinline__ void mbar_wait(unsigned mbar, unsigned parity) {
    asm volatile(
        "{\n\t"
        ".reg .pred P1;\n\t"
        "WAIT_LOOP_%=:\n\t"
        "mbarrier.try_wait.parity.acquire.cta.shared::cta.b64 P1, [%0], %1, 0x989680;\n\t"
        "@P1 bra.uni WAIT_DONE_%=;\n\t"
        "bra.uni WAIT_LOOP_%=;\n\t"
        "WAIT_DONE_%=:\n\t"
        "}"
        :: "r"(mbar), "r"(parity) : "memory");
}

// ---------------- scratch ----------------
__device__ float g_proj [N_ * NPROJ];
__device__ float g_qpt  [N_ * 144];
__device__ float g_kpt  [N_ * 144];
__device__ float g_vpt  [N_ * 288];
__device__ float g_qaug [N_ * H_ * 32];
__device__ float g_kaug [N_ * H_ * 32];
__device__ float g_P    [(long)N_ * H_ * 1024];
__device__ float g_iv   [N_ * H_];
__device__ float g_vm   [(long)N_ * H_ * 64];
__device__ float g_feat [(long)N_ * NFEAT];

// ---------------- kernel A: fused projection GEMM ----------------
__global__ __launch_bounds__(256) void proj_gemm_kernel(
    const float* __restrict__ A,
    const float* __restrict__ wq,  const float* __restrict__ bq,
    const float* __restrict__ wkv, const float* __restrict__ bkv,
    const float* __restrict__ wqp, const float* __restrict__ bqp,
    const float* __restrict__ wkvp,const float* __restrict__ bkvp)
{
    __shared__ float As[16][64];
    __shared__ float Bs[16][68];
    int bm = blockIdx.x * 64, bn = blockIdx.y * 64;
    int tid = threadIdx.x;
    int tx = tid & 15, ty = tid >> 4;
    int lm = tid >> 2, lk4 = (tid & 3) * 4;
    int bk = tid >> 4, bn4 = (tid & 15) * 4;
    u64 acc01[4] = {0,0,0,0}, acc23[4] = {0,0,0,0};

    for (int k0 = 0; k0 < C1_; k0 += 16) {
        float4 av = *(const float4*)&A[(bm + lm) * C1_ + k0 + lk4];
        As[lk4+0][lm] = av.x; As[lk4+1][lm] = av.y;
        As[lk4+2][lm] = av.z; As[lk4+3][lm] = av.w;
        int kg = k0 + bk;
        #pragma unroll
        for (int jj = 0; jj < 4; jj++) {
            int j = bn + bn4 + jj;
            float v;
            if      (j < 192) v = wq  [kg * 192 + j];
            else if (j < 576) v = wkv [kg * 384 + (j - 192)];
            else if (j < 720) v = wqp [kg * 144 + (j - 576)];
            else              v = wkvp[kg * 432 + (j - 720)];
            Bs[bk][bn4 + jj] = v;
        }
        __syncthreads();
        #pragma unroll
        for (int kk = 0; kk < 16; kk++) {
            float4 a4 = *(const float4*)&As[kk][ty * 4];
            ulonglong2 b2 = *(const ulonglong2*)&Bs[kk][tx * 4];
            float a[4] = {a4.x, a4.y, a4.z, a4.w};
            #pragma unroll
            for (int i = 0; i < 4; i++) {
                u64 ai = pack2(a[i]);
                fma2(acc01[i], ai, b2.x);
                fma2(acc23[i], ai, b2.y);
            }
        }
        __syncthreads();
    }
    #pragma unroll
    for (int i = 0; i < 4; i++) {
        float2 lo = *(float2*)&acc01[i];
        float2 hi = *(float2*)&acc23[i];
        float accv[4] = {lo.x, lo.y, hi.x, hi.y};
        #pragma unroll
        for (int j = 0; j < 4; j++) {
            int jg = bn + tx * 4 + j;
            float bias;
            if      (jg < 192) bias = bq  [jg];
            else if (jg < 576) bias = bkv [jg - 192];
            else if (jg < 720) bias = bqp [jg - 576];
            else               bias = bkvp[jg - 720];
            g_proj[(bm + ty * 4 + i) * NPROJ + jg] = accv[j] + bias;
        }
    }
}

// ---------------- kernel B: transform + aug vectors + merged v ----------------
__global__ __launch_bounds__(192) void transform_kernel(
    const float* __restrict__ rot, const float* __restrict__ trans,
    const float* __restrict__ tpw)
{
    int n = blockIdx.x;
    int tid = threadIdx.x;
    __shared__ float sn2[192];

    const float* pr = g_proj + n * NPROJ;
    float r00 = rot[n*9+0], r01 = rot[n*9+1], r02 = rot[n*9+2];
    float r10 = rot[n*9+3], r11 = rot[n*9+4], r12 = rot[n*9+5];
    float r20 = rot[n*9+6], r21 = rot[n*9+7], r22 = rot[n*9+8];
    float t0 = trans[n*3+0], t1 = trans[n*3+1], t2 = trans[n*3+2];

    float nrm = 0.f;
    if (tid < 48) {
        int pp = tid;
        float px = pr[576 +       pp];
        float py = pr[576 +  48 + pp];
        float pz = pr[576 +  96 + pp];
        float gx = r00*px + r01*py + r02*pz + t0;
        float gy = r10*px + r11*py + r12*pz + t1;
        float gz = r20*px + r21*py + r22*pz + t2;
        int h = pp >> 2, p = pp & 3;
        float* o = g_qpt + n * 144 + h * 12 + p * 3;
        o[0] = gx; o[1] = gy; o[2] = gz;
        nrm = gx*gx + gy*gy + gz*gz;
    } else {
        int pp = tid - 48;
        float px = pr[720 +       pp];
        float py = pr[720 + 144 + pp];
        float pz = pr[720 + 288 + pp];
        float gx = r00*px + r01*py + r02*pz + t0;
        float gy = r10*px + r11*py + r12*pz + t1;
        float gz = r20*px + r21*py + r22*pz + t2;
        int h = pp / 12, r = pp % 12;
        if (r < 4) {
            float* o = g_kpt + n * 144 + h * 12 + r * 3;
            o[0] = gx; o[1] = gy; o[2] = gz;
            nrm = gx*gx + gy*gy + gz*gz;
        } else {
            float* o = g_vpt + n * 288 + h * 24 + (r - 4) * 3;
            o[0] = gx; o[1] = gy; o[2] = gz;
        }
    }
    sn2[tid] = nrm;
    __syncthreads();
    if (tid < H_) {
        int h = tid;
        float q2 = 0.f, k2 = 0.f;
        #pragma unroll
        for (int p = 0; p < 4; p++) q2 += sn2[h * 4 + p];
        #pragma unroll
        for (int r = 0; r < 4; r++) k2 += sn2[48 + h * 12 + r];

        float tp = tpw[h];
        float spv = tp > 20.f ? tp : log1pf(__expf(tp));
        float pw = PTW * spv;

        float* qa = g_qaug + (n * H_ + h) * 32;
        float* ka = g_kaug + (n * H_ + h) * 32;
        #pragma unroll
        for (int c = 0; c < 16; c++) {
            qa[c] = SCW * pr[h * 16 + c];
            ka[c] = pr[192 + h * 32 + c];
        }
        #pragma unroll
        for (int c = 0; c < 12; c++) {
            qa[16 + c] = pw * g_qpt[n * 144 + h * 12 + c];
            ka[16 + c] = g_kpt[n * 144 + h * 12 + c];
        }
        qa[28] = -0.5f * pw * q2; qa[29] = 1.f; qa[30] = 0.f; qa[31] = 0.f;
        ka[28] = 1.f; ka[29] = -0.5f * pw * k2; ka[30] = 0.f; ka[31] = 0.f;

        float2* vm = (float2*)&g_vm[((long)n * H_ + h) * 64];
        #pragma unroll
        for (int j = 0; j < 8; j++)
            vm[j] = make_float2(pr[192 + h * 32 + 16 + 2*j],
                                pr[192 + h * 32 + 16 + 2*j + 1]);
        #pragma unroll
        for (int j = 8; j < 20; j++)
            vm[j] = make_float2(g_vpt[n * 288 + h * 24 + 2*(j-8)],
                                g_vpt[n * 288 + h * 24 + 2*(j-8) + 1]);
        #pragma unroll
        for (int j = 20; j < 32; j++)
            vm[j] = make_float2(0.f, 0.f);
    }
}

// ---------------- kernel C: a2d streaming ----------------
__global__ __launch_bounds__(128) void a2d_kernel(
    const float* __restrict__ in2d, const float* __restrict__ w2d,
    const float* __restrict__ b2d)
{
    extern __shared__ float smC[];
    float* sd = smC;
    float* sw = smC + 128 * PITCH;

    int tid = threadIdx.x;
    int n = blockIdx.y;
    int m0 = blockIdx.x * 128;

    for (int i = tid; i < H_ * C2_; i += 128)
        sw[i] = w2d[(i & 127) * H_ + (i >> 7)] * W2DS;

    const float4* g = (const float4*)(in2d + ((long)n * N_ + m0) * C2_);
    for (int i = tid; i < 128 * 32; i += 128) {
        int row = i >> 5, c4 = i & 31;
        float4 v = g[i];
        *(float4*)&sd[row * PITCH + c4 * 4] = v;
    }
    __syncthreads();

    u64 acc[12];
    #pragma unroll
    for (int h = 0; h < 12; h++) acc[h] = 0ULL;

    const ulonglong2* drow = (const ulonglong2*)(sd + tid * PITCH);
    const ulonglong2* swp  = (const ulonglong2*)sw;

    #pragma unroll 4
    for (int c4 = 0; c4 < 32; c4++) {
        ulonglong2 d = drow[c4];
        #pragma unroll
        for (int h = 0; h < 12; h++) {
            ulonglong2 w = swp[h * 32 + c4];
            fma2(acc[h], d.x, w.x);
            fma2(acc[h], d.y, w.y);
        }
    }
    #pragma unroll
    for (int h = 0; h < 12; h++) {
        float2 a = *(float2*)&acc[h];
        g_P[((long)n * H_ + h) * N_ + m0 + tid] = a.x + a.y + b2d[h] * W2DS;
    }
}

// ---------------- kernel D: qk GEMM + mask + EXP ----------------
__global__ __launch_bounds__(256) void qk_kernel(const float* __restrict__ mask)
{
    __shared__ float Aq[32][68];
    __shared__ float Bk[32][68];
    int h  = blockIdx.z;
    int nb = blockIdx.y * 64, mb = blockIdx.x * 64;
    int tid = threadIdx.x;

    for (int i = tid; i < 64 * 8; i += 256) {
        int row = i >> 3, k4 = (i & 7) * 4;
        float4 q = *(const float4*)&g_qaug[((nb + row) * H_ + h) * 32 + k4];
        Aq[k4+0][row] = q.x; Aq[k4+1][row] = q.y; Aq[k4+2][row] = q.z; Aq[k4+3][row] = q.w;
        float4 k = *(const float4*)&g_kaug[((mb + row) * H_ + h) * 32 + k4];
        Bk[k4+0][row] = k.x; Bk[k4+1][row] = k.y; Bk[k4+2][row] = k.z; Bk[k4+3][row] = k.w;
    }
    __syncthreads();

    int tx = tid & 15, ty = tid >> 4;
    float acc[4][4] = {};
    #pragma unroll
    for (int k = 0; k < 32; k++) {
        float4 a4 = *(const float4*)&Aq[k][ty * 4];
        float4 b4 = *(const float4*)&Bk[k][tx * 4];
        float a[4] = {a4.x, a4.y, a4.z, a4.w};
        float b[4] = {b4.x, b4.y, b4.z, b4.w};
        #pragma unroll
        for (int i = 0; i < 4; i++)
            #pragma unroll
            for (int j = 0; j < 4; j++)
                acc[i][j] += a[i] * b[j];
    }
    float mm[4], mn[4];
    #pragma unroll
    for (int j = 0; j < 4; j++) mm[j] = mask[mb + tx * 4 + j];
    #pragma unroll
    for (int i = 0; i < 4; i++) mn[i] = mask[nb + ty * 4 + i];

    #pragma unroll
    for (int i = 0; i < 4; i++) {
        float* p = &g_P[((long)(nb + ty * 4 + i) * H_ + h) * N_ + mb + tx * 4];
        float4 L4 = *(float4*)p;
        L4.x = __expf(L4.x + acc[i][0] - 100000.f * (1.f - mn[i] * mm[0]));
        L4.y = __expf(L4.y + acc[i][1] - 100000.f * (1.f - mn[i] * mm[1]));
        L4.z = __expf(L4.z + acc[i][2] - 100000.f * (1.f - mn[i] * mm[2]));
        L4.w = __expf(L4.w + acc[i][3] - 100000.f * (1.f - mn[i] * mm[3]));
        *(float4*)p = L4;
    }
}

// ---------------- kernel D2: 1/rowsum ----------------
__global__ __launch_bounds__(256) void stats_kernel()
{
    int row  = blockIdx.x * 8 + (threadIdx.x >> 5);
    int lane = threadIdx.x & 31;
    const float4* Pr = (const float4*)(g_P + (long)row * N_);
    float s = 0.f;
    #pragma unroll
    for (int j = 0; j < 8; j++) {
        float4 v = Pr[j * 32 + lane];
        s += v.x + v.y + v.z + v.w;
    }
    #pragma unroll
    for (int o = 16; o > 0; o >>= 1)
        s += __shfl_xor_sync(0xffffffffu, s, o);
    if (lane == 0) g_iv[row] = 1.f / s;
}

// ---------------- kernel E: attention (TMA bulk double-buffered, TM=16) ----------------
__global__ void __launch_bounds__(384, 2) attn_kernel(
    const float* __restrict__ in2d,
    const float* __restrict__ rot, const float* __restrict__ trans)
{
    extern __shared__ float sm[];
    float* s2d  = sm;                      // 2 * 8192 floats (2 x 32KB)
    float* spH  = sm + 2 * BUFF;           // 12*16*8 = 1536
    float* sinv = spH + H_ * TM * 8;       // 48
    u64*   mbar = (u64*)(sinv + QB * H_);  // 2 mbarriers

    int tid  = threadIdx.x;
    int h    = tid >> 5;
    int lane = tid & 31;
    int n0   = blockIdx.x * QB;

    int c4 = tid & 31;
    int hp = (tid >> 5) % 6;
    int mq = tid / 192;
    int h0 = hp * 2;

    unsigned s2d_sm  = smem_u32(s2d);
    unsigned mbar_sm = smem_u32(mbar);
    const u64* vm64 = (const u64*)g_vm;
    const ulonglong2* pbase = (const ulonglong2*)spH;   // [h*16+mi][2]

    if (tid == 0) {
        mbar_init(mbar_sm, 1);
        mbar_init(mbar_sm + 8, 1);
    }
    __syncthreads();

    // prefetch tile 0 into buffer 0
    if (tid == 0) {
        mbar_expect_tx(mbar_sm, QB * TM * C2_ * 4);
        #pragma unroll
        for (int q = 0; q < QB; q++)
            bulk_cp(s2d_sm + q * TM * C2_ * 4,
                    in2d + ((long)(n0 + q) * N_) * C2_,
                    TM * C2_ * 4, mbar_sm);
    }

    ulonglong2 a2[2][QB];
    #pragma unroll
    for (int hh = 0; hh < 2; hh++)
        #pragma unroll
        for (int q = 0; q < QB; q++) a2[hh][q] = make_ulonglong2(0ULL, 0ULL);
    u64 acc2b[QB] = {0,0,0,0};

    for (int t = 0; t < NT; t++) {
        int m0 = t * TM;
        int cur = t & 1;

        // prefetch t+1 into alternate buffer (its readers finished at t-1)
        if (tid == 0 && t + 1 < NT) {
            unsigned mb = mbar_sm + (1 - cur) * 8;
            unsigned db = s2d_sm + (1 - cur) * BUFF * 4;
            mbar_expect_tx(mb, QB * TM * C2_ * 4);
            #pragma unroll
            for (int q = 0; q < QB; q++)
                bulk_cp(db + q * TM * C2_ * 4,
                        in2d + ((long)(n0 + q) * N_ + m0 + TM) * C2_,
                        TM * C2_ * 4, mb);
        }

        // phase 2: p production (h = warp, mi = lane < 16)
        if (lane < TM) {
            int m = m0 + lane;
            float pv[QB];
            #pragma unroll
            for (int q = 0; q < QB; q++)
                pv[q] = g_P[((long)(n0 + q) * H_ + h) * N_ + m];
            float* dst = &spH[(h * TM + lane) * 8];
            *(float4*)dst       = make_float4(pv[0], pv[0], pv[1], pv[1]);
            *(float4*)(dst + 4) = make_float4(pv[2], pv[2], pv[3], pv[3]);
        }

        // wait for current tile data
        mbar_wait(mbar_sm + cur * 8, (t >> 1) & 1);
        __syncthreads();

        const float* buf = s2d + cur * BUFF;
        const ulonglong2* s2d8 = (const ulonglong2*)buf;  // 32 ul2 per row

        // phase 3: attn_2d (2 heads/thread, m-split)
        {
            int mbeg = mq * (TM / 2);
            #pragma unroll
            for (int mi = mbeg; mi < mbeg + TM / 2; mi++) {
                ulonglong2 pA0 = pbase[(h0 * TM + mi) * 2 + 0];
                ulonglong2 pA1 = pbase[(h0 * TM + mi) * 2 + 1];
                ulonglong2 pB0 = pbase[((h0 + 1) * TM + mi) * 2 + 0];
                ulonglong2 pB1 = pbase[((h0 + 1) * TM + mi) * 2 + 1];
                u64 pH0[4] = {pA0.x, pA0.y, pA1.x, pA1.y};
                u64 pH1[4] = {pB0.x, pB0.y, pB1.x, pB1.y};
                #pragma unroll
                for (int q = 0; q < QB; q++) {
                    ulonglong2 d = s2d8[(q * TM + mi) * 32 + c4];
                    fma2(a2[0][q].x, pH0[q], d.x);
                    fma2(a2[0][q].y, pH0[q], d.y);
                    fma2(a2[1][q].x, pH1[q], d.x);
                    fma2(a2[1][q].y, pH1[q], d.y);
                }
            }
        }

        // phase 2b: merged-v accumulation (lane = u64 channel pair)
        {
            const u64* vrow = vm64 + ((long)m0 * H_ + h) * 32 + lane;
            #pragma unroll
            for (int mi = 0; mi < TM; mi++) {
                u64 v = vrow[(long)mi * H_ * 32];
                ulonglong2 pq01 = pbase[(h * TM + mi) * 2 + 0];
                ulonglong2 pq23 = pbase[(h * TM + mi) * 2 + 1];
                fma2(acc2b[0], pq01.x, v);
                fma2(acc2b[1], pq01.y, v);
                fma2(acc2b[2], pq23.x, v);
                fma2(acc2b[3], pq23.y, v);
            }
        }
        __syncthreads();
    }

    // ---- epilogue ----
    float inv[QB];
    #pragma unroll
    for (int q = 0; q < QB; q++) {
        inv[q] = g_iv[(n0 + q) * H_ + h];
        if (lane == 0) sinv[q * H_ + h] = inv[q];
    }
    #pragma unroll
    for (int q = 0; q < QB; q++) {
        int n = n0 + q;
        float* f = g_feat + (long)n * NFEAT;
        float2 ac = *(float2*)&acc2b[q];
        ac.x *= inv[q]; ac.y *= inv[q];
        if (lane < 8) {
            f[h * 16 + 2 * lane]     = ac.x;
            f[h * 16 + 2 * lane + 1] = ac.y;
        }
        __syncwarp();
        if (lane >= 8 && lane < 20) {
            spH[h * 64 + 2 * (lane - 8)]     = ac.x;
            spH[h * 64 + 2 * (lane - 8) + 1] = ac.y;
        }
        __syncwarp();
        if (lane < 8) {
            int p = lane;
            float gx = spH[h * 64 + p * 3 + 0] - trans[n * 3 + 0];
            float gy = spH[h * 64 + p * 3 + 1] - trans[n * 3 + 1];
            float gz = spH[h * 64 + p * 3 + 2] - trans[n * 3 + 2];
            float lx = rot[n*9+0]*gx + rot[n*9+3]*gy + rot[n*9+6]*gz;
            float ly = rot[n*9+1]*gx + rot[n*9+4]*gy + rot[n*9+7]*gz;
            float lz = rot[n*9+2]*gx + rot[n*9+5]*gy + rot[n*9+8]*gz;
            float d  = sqrtf(1e-8f + lx*lx + ly*ly + lz*lz);
            f[192 + h * 8 + p] = lx;
            f[288 + h * 8 + p] = ly;
            f[384 + h * 8 + p] = lz;
            f[480 + h * 8 + p] = d;
        }
        __syncwarp();
    }
    __syncthreads();

    float4* red = (float4*)s2d;
    #pragma unroll
    for (int hh = 0; hh < 2; hh++) {
        __syncthreads();
        #pragma unroll
        for (int q = 0; q < QB; q++) {
            u64 iv2 = pack2(sinv[q * H_ + h0 + hh]);
            u64 vx = a2[hh][q].x, vy = a2[hh][q].y;
            mul2(vx, iv2); mul2(vy, iv2);
            float2 lo = *(float2*)&vx;
            float2 hi = *(float2*)&vy;
            red[(q * 2 + mq) * 192 + hp * 32 + c4] = make_float4(lo.x, lo.y, hi.x, hi.y);
        }
        __syncthreads();
        if (mq == 0) {
            #pragma unroll
            for (int q = 0; q < QB; q++) {
                float4 a = red[(q * 2    ) * 192 + hp * 32 + c4];
                float4 b = red[(q * 2 + 1) * 192 + hp * 32 + c4];
                a.x += b.x; a.y += b.y; a.z += b.z; a.w += b.w;
                *(float4*)&g_feat[(long)(n0 + q) * NFEAT + 576 + (h0 + hh) * 128 + c4 * 4] = a;
            }
        }
    }
}

// ---------------- kernel F: output GEMM ----------------
__global__ __launch_bounds__(1024) void out_gemm_kernel(
    const float* __restrict__ B, const float* __restrict__ bias,
    float* __restrict__ C)
{
    __shared__ float As[4][16][64];
    __shared__ float Bs[4][16][36];
    int tid = threadIdx.x;
    int g = tid >> 8;
    int t = tid & 255;
    int bm = blockIdx.x * 64, bn = blockIdx.y * 32;
    int tx = t & 15, ty = t >> 4;
    int lm = t >> 2, lk4 = (t & 3) * 4;
    u64 acc[4] = {0,0,0,0};

    int kbase = g * 528;
    for (int kk0 = 0; kk0 < 528; kk0 += 16) {
        int k0 = kbase + kk0;
        float4 av = *(const float4*)&g_feat[(long)(bm + lm) * NFEAT + k0 + lk4];
        As[g][lk4+0][lm] = av.x; As[g][lk4+1][lm] = av.y;
        As[g][lk4+2][lm] = av.z; As[g][lk4+3][lm] = av.w;
        if (t < 128) {
            int bk = t >> 3, bn4 = (t & 7) * 4;
            float4 bv = *(const float4*)&B[(long)(k0 + bk) * COUT_ + bn + bn4];
            *(float4*)&Bs[g][bk][bn4] = bv;
        }
        __syncthreads();
        #pragma unroll
        for (int kk = 0; kk < 16; kk++) {
            float4 a4 = *(const float4*)&As[g][kk][ty * 4];
            u64 b = *(const u64*)&Bs[g][kk][tx * 2];
            fma2(acc[0], pack2(a4.x), b);
            fma2(acc[1], pack2(a4.y), b);
            fma2(acc[2], pack2(a4.z), b);
            fma2(acc[3], pack2(a4.w), b);
        }
        __syncthreads();
    }

    float* red = &As[0][0][0];
    #pragma unroll
    for (int r = 0; r < 2; r++) {
        __syncthreads();
        if (g > 0) {
            float2 p0 = *(float2*)&acc[r * 2];
            float2 p1 = *(float2*)&acc[r * 2 + 1];
            *(float4*)&red[((g - 1) * 256 + t) * 4] = make_float4(p0.x, p0.y, p1.x, p1.y);
        }
        __syncthreads();
        if (g == 0) {
            #pragma unroll
            for (int gg = 0; gg < 3; gg++) {
                float4 v = *(float4*)&red[(gg * 256 + t) * 4];
                float2 p0 = *(float2*)&acc[r * 2];
                float2 p1 = *(float2*)&acc[r * 2 + 1];
                p0.x += v.x; p0.y += v.y; p1.x += v.z; p1.y += v.w;
                *(float2*)&acc[r * 2]     = p0;
                *(float2*)&acc[r * 2 + 1] = p1;
            }
        }
    }
    if (g == 0) {
        float b0 = bias[bn + tx * 2], b1 = bias[bn + tx * 2 + 1];
        #pragma unroll
        for (int i = 0; i < 4; i++) {
            float2 v = *(float2*)&acc[i];
            v.x += b0; v.y += b1;
            *(float2*)&C[(long)(bm + ty * 4 + i) * COUT_ + bn + tx * 2] = v;
        }
    }
}

// ---------------- launch ----------------
extern "C" void kernel_launch(void* const* d_in, const int* in_sizes, int n_in,
                              void* d_out, int out_size)
{
    const float* inputs_1d = (const float*)d_in[0];
    const float* inputs_2d = (const float*)d_in[1];
    const float* mask      = (const float*)d_in[2];
    const float* rot       = (const float*)d_in[3];
    const float* trans     = (const float*)d_in[4];
    const float* wq        = (const float*)d_in[5];
    const float* bq        = (const float*)d_in[6];
    const float* wkv       = (const float*)d_in[7];
    const float* bkv       = (const float*)d_in[8];
    const float* wqp       = (const float*)d_in[9];
    const float* bqp       = (const float*)d_in[10];
    const float* wkvp      = (const float*)d_in[11];
    const float* bkvp      = (const float*)d_in[12];
    const float* w2d       = (const float*)d_in[13];
    const float* b2d       = (const float*)d_in[14];
    const float* tpw       = (const float*)d_in[15];
    const float* wout      = (const float*)d_in[16];
    const float* bout      = (const float*)d_in[17];
    float* out = (float*)d_out;

    proj_gemm_kernel<<<dim3(16, 18), 256>>>(inputs_1d, wq, bq, wkv, bkv,
                                            wqp, bqp, wkvp, bkvp);
    transform_kernel<<<N_, 192>>>(rot, trans, tpw);

    int smemC = (128 * PITCH + H_ * C2_) * (int)sizeof(float);
    cudaFuncSetAttribute(a2d_kernel, cudaFuncAttributeMaxDynamicSharedMemorySize, smemC);
    a2d_kernel<<<dim3(8, N_), 128, smemC>>>(inputs_2d, w2d, b2d);

    qk_kernel<<<dim3(16, 16, 12), 256>>>(mask);
    stats_kernel<<<(N_ * H_) / 8, 256>>>();

    int smemE = (2 * BUFF + H_ * TM * 8 + QB * H_ + 4) * (int)sizeof(float);
    cudaFuncSetAttribute(attn_kernel, cudaFuncAttributeMaxDynamicSharedMemorySize, smemE);
    attn_kernel<<<N_ / QB, 384, smemE>>>(inputs_2d, rot, trans);

    out_gemm_kernel<<<dim3(16, 12), 1024>>>(wout, bout, out);
}